// round 3
// baseline (speedup 1.0000x reference)
#include <cuda_runtime.h>
#include <math.h>

// SSKernelNPLR: H=256, S=256 (rep=1), N=64, R=1, CH=1, L=2048
#define HH 256
#define NN 64
#define LL 2048

// Packed half-spectrum Z[h][k], k in [0,1024): irfft(X, 2048) == interleaved
// 1024-point complex IDFT of Z.
__device__ float2 g_Z[HH * 1024];

// ---- packed f32x2 helpers (sm_100+) ----
__device__ __forceinline__ unsigned long long pack2(float lo, float hi) {
    unsigned long long r;
    asm("mov.b64 %0, {%1, %2};" : "=l"(r) : "f"(lo), "f"(hi));
    return r;
}
__device__ __forceinline__ void unpack2(unsigned long long v, float& lo, float& hi) {
    asm("mov.b64 {%0, %1}, %2;" : "=f"(lo), "=f"(hi) : "l"(v));
}
__device__ __forceinline__ unsigned long long ffma2(
    unsigned long long a, unsigned long long b, unsigned long long c) {
    unsigned long long d;
    asm("fma.rn.f32x2 %0, %1, %2, %3;" : "=l"(d) : "l"(a), "l"(b), "l"(c));
    return d;
}
__device__ __forceinline__ float frcp_a(float x) {
    float r;
    asm("rcp.approx.f32 %0, %1;" : "=f"(r) : "f"(x));
    return r;
}

// ---------------------------------------------------------------------------
// Kernel 1: Cauchy + Woodbury + bilinear -> directly emits packed spectrum Z.
// Thread handles the pole-pair (l0, 1024-l0):
//   y0 = 2*tan(pi*l0/2048),  y1 = 2/tan(pi*l0/2048)  (= y at 1024-l0)
// Per slot, per n (conjugate pair folded, dt folded into constants):
//   acc += (Nr + i*vy*y) / ((K1 - y^2) + i*K2*y)
// Then Woodbury + (1 + i*y/2), then real-packing:
//   S = X0 + conj(X1), T = e^{i pi l0/1024} * (X0 - conj(X1))
//   Z[l0]      = (Sx - Ty, Sy + Tx)/2048
//   Z[1024-l0] = (Sx + Ty, Tx - Sy)/2048     (skip when l0 == 0)
// ---------------------------------------------------------------------------
__global__ void __launch_bounds__(160) cauchy_kernel(
    const float* __restrict__ Cin, const float* __restrict__ Bin,
    const float* __restrict__ Pin, const float* __restrict__ iwr,
    const float* __restrict__ wim, const float* __restrict__ logdt)
{
    __shared__ float2 sK[NN];        // (K1, K2)
    __shared__ float4 sP[4][NN];     // (Nr, Nr, vy, vy) for v00,v01,v10,v11

    const int h = blockIdx.x;
    const int tid = threadIdx.x;

    if (tid < NN) {
        const int n = tid;
        const int idx = h * NN + n;
        const float dt = expf(logdt[h]);
        const float a = -expf(iwr[idx]) * dt;
        const float b = wim[idx] * dt;
        sK[n] = make_float2(fmaf(a, a, b * b), -2.0f * a);

        const float Br = Bin[2*idx], Bi = Bin[2*idx+1];
        const float Cr = Cin[2*idx], Ci = Cin[2*idx+1];
        const float Pr = Pin[2*idx], Pi = Pin[2*idx+1];

        float p, q, Nr, vy;
        p = Br*Cr - Bi*Ci;  q = Br*Ci + Bi*Cr;               // v00 = B*C
        Nr = -2.0f*(p*a + q*b)*dt; vy = 2.0f*p*dt;
        sP[0][n] = make_float4(Nr, Nr, vy, vy);
        p = Br*Pr + Bi*Pi;  q = Bi*Pr - Br*Pi;               // v01 = B*conj(P)
        Nr = -2.0f*(p*a + q*b)*dt; vy = 2.0f*p*dt;
        sP[1][n] = make_float4(Nr, Nr, vy, vy);
        p = Pr*Cr - Pi*Ci;  q = Pr*Ci + Pi*Cr;               // v10 = P*C
        Nr = -2.0f*(p*a + q*b)*dt; vy = 2.0f*p*dt;
        sP[2][n] = make_float4(Nr, Nr, vy, vy);
        p = Pr*Pr + Pi*Pi;                                   // v11 = |P|^2
        Nr = -2.0f*p*a*dt; vy = 2.0f*p*dt;
        sP[3][n] = make_float4(Nr, Nr, vy, vy);
    }
    __syncthreads();
    if (tid > 128) return;

    const int l0 = blockIdx.y * 128 + tid;     // [0, 512]; boundary dups benign
    const float t = tanf((float)l0 * (3.14159265358979323846f / 2048.0f));
    const float y0 = 2.0f * t;
    float y1 = 2.0f * frcp_a(t);               // l0=0 -> inf -> clamp (Nyquist)
    y1 = fminf(y1, 3.0e7f);
    const float yy0 = y0 * y0;
    const float yy1 = y1 * y1;

    const ulonglong2* __restrict__ p0 = reinterpret_cast<const ulonglong2*>(sP[0]);
    const ulonglong2* __restrict__ p1 = reinterpret_cast<const ulonglong2*>(sP[1]);
    const ulonglong2* __restrict__ p2 = reinterpret_cast<const ulonglong2*>(sP[2]);
    const ulonglong2* __restrict__ p3 = reinterpret_cast<const ulonglong2*>(sP[3]);

    unsigned long long a0 = 0ull, a1 = 0ull, a2 = 0ull, a3 = 0ull;  // slot0
    unsigned long long b0 = 0ull, b1 = 0ull, b2 = 0ull, b3 = 0ull;  // slot1

    #pragma unroll 8
    for (int n = 0; n < NN; n++) {
        const float2 kk = sK[n];
        // slot0
        const float dr0 = kk.x - yy0;
        const float di0 = kk.y * y0;
        const float iv0 = frcp_a(fmaf(dr0, dr0, di0 * di0));
        const float cr0 = dr0 * iv0;
        const float nc0 = -di0 * iv0;
        const unsigned long long Pc0 = pack2(cr0, nc0);
        const unsigned long long Pu0 = pack2(-y0 * nc0, y0 * cr0);
        // slot1
        const float dr1 = kk.x - yy1;
        const float di1 = kk.y * y1;
        const float iv1 = frcp_a(fmaf(dr1, dr1, di1 * di1));
        const float cr1 = dr1 * iv1;
        const float nc1 = -di1 * iv1;
        const unsigned long long Pc1 = pack2(cr1, nc1);
        const unsigned long long Pu1 = pack2(-y1 * nc1, y1 * cr1);

        ulonglong2 q;
        q = p0[n];
        a0 = ffma2(q.x, Pc0, a0); a0 = ffma2(q.y, Pu0, a0);
        b0 = ffma2(q.x, Pc1, b0); b0 = ffma2(q.y, Pu1, b0);
        q = p1[n];
        a1 = ffma2(q.x, Pc0, a1); a1 = ffma2(q.y, Pu0, a1);
        b1 = ffma2(q.x, Pc1, b1); b1 = ffma2(q.y, Pu1, b1);
        q = p2[n];
        a2 = ffma2(q.x, Pc0, a2); a2 = ffma2(q.y, Pu0, a2);
        b2 = ffma2(q.x, Pc1, b2); b2 = ffma2(q.y, Pu1, b2);
        q = p3[n];
        a3 = ffma2(q.x, Pc0, a3); a3 = ffma2(q.y, Pu0, a3);
        b3 = ffma2(q.x, Pc1, b3); b3 = ffma2(q.y, Pu1, b3);
    }

    // Woodbury + bilinear per slot
    float2 X[2];
    #pragma unroll
    for (int s = 0; s < 2; s++) {
        float r0r, r0i, r1r, r1i, r2r, r2i, r3r, r3i;
        if (s == 0) {
            unpack2(a0, r0r, r0i); unpack2(a1, r1r, r1i);
            unpack2(a2, r2r, r2i); unpack2(a3, r3r, r3i);
        } else {
            unpack2(b0, r0r, r0i); unpack2(b1, r1r, r1i);
            unpack2(b2, r2r, r2i); unpack2(b3, r3r, r3i);
        }
        const float dre  = 1.0f + r3r;
        const float dim_ = r3i;
        const float dm = frcp_a(fmaf(dre, dre, dim_ * dim_));
        const float tr = r1r * r2r - r1i * r2i;
        const float ti = r1r * r2i + r1i * r2r;
        const float wr = (tr * dre + ti * dim_) * dm;
        const float wi = (ti * dre - tr * dim_) * dm;
        const float kr = r0r - wr;
        const float ki = r0i - wi;
        const float hy = 0.5f * (s == 0 ? y0 : y1);   // * (1 + i*y/2)
        X[s] = make_float2(kr - ki * hy, ki + kr * hy);
    }

    // Real-packing combine
    const float Sx = X[0].x + X[1].x, Sy = X[0].y - X[1].y;
    const float Dx = X[0].x - X[1].x, Dy = X[0].y + X[1].y;
    float ts, tc;
    sincospif((float)l0 * (1.0f / 1024.0f), &ts, &tc);   // e^{i pi l0/1024}
    const float Tx = tc * Dx - ts * Dy;
    const float Ty = tc * Dy + ts * Dx;
    const float sc = 1.0f / 2048.0f;
    float2* __restrict__ Z = &g_Z[h * 1024];
    Z[l0] = make_float2((Sx - Ty) * sc, (Sy + Tx) * sc);
    if (l0 != 0)
        Z[1024 - l0] = make_float2((Sx + Ty) * sc, (Tx - Sy) * sc);
}

// ---------------------------------------------------------------------------
// Kernel 2: 1024-point complex IDFT of Z per h (two-step 32x32), m-split 4-way.
//   A[k1][m] = sum_{k2<32} Z[k1+32k2] e^{2pi i k2 m/32}
//   z[n]     = sum_{k1<32} A[k1][n&31] e^{2pi i k1 n/1024}
//   out[2n] = Re z[n], out[2n+1] = Im z[n]
// Block (h, j) handles m in [8j, 8j+8): zero duplicated work, 4x occupancy.
// ---------------------------------------------------------------------------
__global__ void __launch_bounds__(256) irfft_kernel(float* __restrict__ out)
{
    __shared__ float2 sA[32][8];    // 2 KB

    const int h = blockIdx.x;
    const int j = blockIdx.y;
    const int tid = threadIdx.x;
    const int m8 = tid & 7;
    const int r  = tid >> 3;        // [0,32)
    const int m  = j * 8 + m8;
    const float2* __restrict__ Z = &g_Z[h * 1024];

    // Step A: one sA entry per thread (k1 = r)
    {
        float rs, rc;
        sincospif((float)m * (1.0f / 16.0f), &rs, &rc);   // e^{2pi i m/32}
        float cr = 1.0f, ci = 0.0f, ar = 0.0f, ai = 0.0f;
        #pragma unroll 8
        for (int k2 = 0; k2 < 32; k2++) {
            const float2 x = Z[r + 32 * k2];              // broadcast LDG
            ar = fmaf(x.x, cr, fmaf(-x.y, ci, ar));
            ai = fmaf(x.x, ci, fmaf( x.y, cr, ai));
            const float ncr = fmaf(cr, rc, -ci * rs);
            const float nci = fmaf(cr, rs,  ci * rc);
            cr = ncr; ci = nci;
        }
        sA[r][m8] = make_float2(ar, ai);
    }
    __syncthreads();

    // Step B: one output per thread (q = r)
    {
        const int n = (r << 5) + m;
        float rs, rc;
        sincospif((float)n * (1.0f / 512.0f), &rs, &rc);  // e^{2pi i n/1024}
        float cr = 1.0f, ci = 0.0f, zr = 0.0f, zi = 0.0f;
        #pragma unroll 8
        for (int k1 = 0; k1 < 32; k1++) {
            const float2 a = sA[k1][m8];                  // conflict-free
            zr = fmaf(a.x, cr, fmaf(-a.y, ci, zr));
            zi = fmaf(a.x, ci, fmaf( a.y, cr, zi));
            const float ncr = fmaf(cr, rc, -ci * rs);
            const float nci = fmaf(cr, rs,  ci * rc);
            cr = ncr; ci = nci;
        }
        reinterpret_cast<float2*>(out + h * LL)[n] = make_float2(zr, zi);
    }
}

// ---------------------------------------------------------------------------
// Inputs: 0:C 1:B 2:P 3:inv_w_real 4:w_imag 5:log_dt 6:L(ignored)
// Output: (1, 256, 2048) f32
// ---------------------------------------------------------------------------
extern "C" void kernel_launch(void* const* d_in, const int* in_sizes, int n_in,
                              void* d_out, int out_size)
{
    const float* C     = (const float*)d_in[0];
    const float* B     = (const float*)d_in[1];
    const float* P     = (const float*)d_in[2];
    const float* iwr   = (const float*)d_in[3];
    const float* wimag = (const float*)d_in[4];
    const float* logdt = (const float*)d_in[5];
    float* out = (float*)d_out;

    dim3 grid1(HH, 4);
    cauchy_kernel<<<grid1, 160>>>(C, B, P, iwr, wimag, logdt);
    dim3 grid2(HH, 4);
    irfft_kernel<<<grid2, 256>>>(out);
}

// round 4
// speedup vs baseline: 1.1093x; 1.1093x over previous
#include <cuda_runtime.h>
#include <math.h>

// SSKernelNPLR: H=256, S=256 (rep=1), N=64, R=1, CH=1, L=2048
#define HH 256
#define NN 64
#define LL 2048

// Packed half-spectrum Z[h][k], k in [0,1024): irfft(X, 2048) == interleaved
// 1024-point complex IDFT of Z.
__device__ float2 g_Z[HH * 1024];

// ---- packed f32x2 helpers (sm_100+) ----
__device__ __forceinline__ unsigned long long pack2(float lo, float hi) {
    unsigned long long r;
    asm("mov.b64 %0, {%1, %2};" : "=l"(r) : "f"(lo), "f"(hi));
    return r;
}
__device__ __forceinline__ void unpack2(unsigned long long v, float& lo, float& hi) {
    asm("mov.b64 {%0, %1}, %2;" : "=f"(lo), "=f"(hi) : "l"(v));
}
__device__ __forceinline__ unsigned long long ffma2(
    unsigned long long a, unsigned long long b, unsigned long long c) {
    unsigned long long d;
    asm("fma.rn.f32x2 %0, %1, %2, %3;" : "=l"(d) : "l"(a), "l"(b), "l"(c));
    return d;
}
__device__ __forceinline__ float frcp_a(float x) {
    float r;
    asm("rcp.approx.f32 %0, %1;" : "=f"(r) : "f"(x));
    return r;
}

// ---------------------------------------------------------------------------
// Kernel 1: Cauchy + Woodbury + bilinear -> packed spectrum Z (fused via
// smem pair exchange). Single l per thread (8 u64 accumulators).
//
// grid (HH, 5): by<4 main blocks; t<128 -> lA = by*128+t, t>=128 -> 1024-lA.
// by==4: one warp computes the self-paired point l=512; Z[512]=(Xr,-Xi)/1024.
//
// Per n (conjugate pair folded, dt folded):
//   (dr,di) = ffma2((K1,K2),(1,y),(-y^2,0))
//   inv = rcp(dr^2+di^2); Pc = (dr*inv, di*inv) = (cr,ci)
//   acc_a += (Nr,-Nr)*Pc ; acc_b += (vy,vy)*Pc        [per v-slot]
// Epilogue per slot: re = a.x + y*b.y ; im = a.y + y*b.x
// ---------------------------------------------------------------------------
__global__ void __launch_bounds__(256) cauchy_kernel(
    const float* __restrict__ Cin, const float* __restrict__ Bin,
    const float* __restrict__ Pin, const float* __restrict__ iwr,
    const float* __restrict__ wim, const float* __restrict__ logdt)
{
    __shared__ float2 sK[NN];        // (K1, K2)
    __shared__ float4 sP[4][NN];     // (Nr, -Nr, vy, vy) for v00,v01,v10,v11
    __shared__ float2 sX[256];       // pair exchange

    const int h = blockIdx.x;
    const int tid = threadIdx.x;

    if (tid < NN) {
        const int n = tid;
        const int idx = h * NN + n;
        const float dt = expf(logdt[h]);
        const float a = -expf(iwr[idx]) * dt;
        const float b = wim[idx] * dt;
        sK[n] = make_float2(fmaf(a, a, b * b), -2.0f * a);

        const float Br = Bin[2*idx], Bi = Bin[2*idx+1];
        const float Cr = Cin[2*idx], Ci = Cin[2*idx+1];
        const float Pr = Pin[2*idx], Pi = Pin[2*idx+1];

        float p, q, Nr, vy;
        p = Br*Cr - Bi*Ci;  q = Br*Ci + Bi*Cr;               // v00 = B*C
        Nr = -2.0f*(p*a + q*b)*dt; vy = 2.0f*p*dt;
        sP[0][n] = make_float4(Nr, -Nr, vy, vy);
        p = Br*Pr + Bi*Pi;  q = Bi*Pr - Br*Pi;               // v01 = B*conj(P)
        Nr = -2.0f*(p*a + q*b)*dt; vy = 2.0f*p*dt;
        sP[1][n] = make_float4(Nr, -Nr, vy, vy);
        p = Pr*Cr - Pi*Ci;  q = Pr*Ci + Pi*Cr;               // v10 = P*C
        Nr = -2.0f*(p*a + q*b)*dt; vy = 2.0f*p*dt;
        sP[2][n] = make_float4(Nr, -Nr, vy, vy);
        p = Pr*Pr + Pi*Pi;                                   // v11 = |P|^2
        Nr = -2.0f*p*a*dt; vy = 2.0f*p*dt;
        sP[3][n] = make_float4(Nr, -Nr, vy, vy);
    }
    __syncthreads();

    const int by = blockIdx.y;
    const bool special = (by == 4);
    int l;
    if (special) {
        if (tid >= 32) return;       // one warp suffices; no syncs below on this path
        l = 512;
    } else {
        const int tq = tid & 127;
        const int lA = by * 128 + tq;
        l = (tid < 128) ? lA : (1024 - lA);
    }

    float y = 2.0f * tanf((float)l * (3.14159265358979323846f / 2048.0f));
    y = fminf(fmaxf(y, -3.0e7f), 3.0e7f);     // guard l -> 1024 pole
    const unsigned long long Y1 = pack2(1.0f, y);
    const unsigned long long YY = pack2(-y * y, 0.0f);

    const ulonglong2* __restrict__ p0 = reinterpret_cast<const ulonglong2*>(sP[0]);
    const ulonglong2* __restrict__ p1 = reinterpret_cast<const ulonglong2*>(sP[1]);
    const ulonglong2* __restrict__ p2 = reinterpret_cast<const ulonglong2*>(sP[2]);
    const ulonglong2* __restrict__ p3 = reinterpret_cast<const ulonglong2*>(sP[3]);
    const unsigned long long* __restrict__ pk =
        reinterpret_cast<const unsigned long long*>(sK);

    unsigned long long A0 = 0ull, B0 = 0ull, A1 = 0ull, B1 = 0ull;
    unsigned long long A2 = 0ull, B2 = 0ull, A3 = 0ull, B3 = 0ull;

    #pragma unroll 8
    for (int n = 0; n < NN; n++) {
        const unsigned long long D = ffma2(pk[n], Y1, YY);   // (dr, di)
        float dr, di;
        unpack2(D, dr, di);
        const float inv = frcp_a(fmaf(dr, dr, di * di));
        const unsigned long long Pc = pack2(dr * inv, di * inv);  // (cr, ci)

        ulonglong2 q;
        q = p0[n]; A0 = ffma2(q.x, Pc, A0); B0 = ffma2(q.y, Pc, B0);
        q = p1[n]; A1 = ffma2(q.x, Pc, A1); B1 = ffma2(q.y, Pc, B1);
        q = p2[n]; A2 = ffma2(q.x, Pc, A2); B2 = ffma2(q.y, Pc, B2);
        q = p3[n]; A3 = ffma2(q.x, Pc, A3); B3 = ffma2(q.y, Pc, B3);
    }

    float ax, ay, bx, byy;
    float r0r, r0i, r1r, r1i, r2r, r2i, r3r, r3i;
    unpack2(A0, ax, ay); unpack2(B0, bx, byy);
    r0r = fmaf(y, byy, ax);  r0i = fmaf(y, bx, ay);
    unpack2(A1, ax, ay); unpack2(B1, bx, byy);
    r1r = fmaf(y, byy, ax);  r1i = fmaf(y, bx, ay);
    unpack2(A2, ax, ay); unpack2(B2, bx, byy);
    r2r = fmaf(y, byy, ax);  r2i = fmaf(y, bx, ay);
    unpack2(A3, ax, ay); unpack2(B3, bx, byy);
    r3r = fmaf(y, byy, ax);  r3i = fmaf(y, bx, ay);

    // Woodbury: kf = r00 - r01*r10/(1 + r11)
    const float dre  = 1.0f + r3r;
    const float dim_ = r3i;
    const float dm = frcp_a(fmaf(dre, dre, dim_ * dim_));
    const float tr = r1r * r2r - r1i * r2i;
    const float ti = r1r * r2i + r1i * r2r;
    const float wr = (tr * dre + ti * dim_) * dm;
    const float wi = (ti * dre - tr * dim_) * dm;
    const float kr = r0r - wr;
    const float ki = r0i - wi;

    // * 2/(1+omega) = (1 + i*y/2)
    const float hy = 0.5f * y;
    const float2 X = make_float2(kr - ki * hy, ki + kr * hy);

    float2* __restrict__ Z = &g_Z[h * 1024];

    if (special) {
        // Z[512] from self-paired X[512]
        if (tid == 0)
            Z[512] = make_float2(X.x * (1.0f / 1024.0f), -X.y * (1.0f / 1024.0f));
        return;
    }

    sX[tid] = X;
    __syncthreads();

    if (tid < 128) {
        const int lA = by * 128 + tid;
        const float2 X1 = sX[tid + 128];      // X[1024 - lA]
        const float Sx = X.x + X1.x, Sy = X.y - X1.y;
        const float Dx = X.x - X1.x, Dy = X.y + X1.y;
        float ts, tc;
        sincospif((float)lA * (1.0f / 1024.0f), &ts, &tc);   // e^{i pi lA/1024}
        const float Tx = tc * Dx - ts * Dy;
        const float Ty = tc * Dy + ts * Dx;
        const float sc = 1.0f / 2048.0f;
        Z[lA] = make_float2((Sx - Ty) * sc, (Sy + Tx) * sc);
        if (lA != 0)
            Z[1024 - lA] = make_float2((Sx + Ty) * sc, (Tx - Sy) * sc);
    }
}

// ---------------------------------------------------------------------------
// Kernel 2: 1024-point complex IDFT of Z per h (two-step 32x32), m-split 4-way.
//   A[k1][m] = sum_{k2<32} Z[k1+32k2] e^{2pi i k2 m/32}
//   z[n]     = sum_{k1<32} A[k1][n&31] e^{2pi i k1 n/1024}
//   out[2n] = Re z[n], out[2n+1] = Im z[n]
// ---------------------------------------------------------------------------
__global__ void __launch_bounds__(256) irfft_kernel(float* __restrict__ out)
{
    __shared__ float2 sA[32][8];    // 2 KB

    const int h = blockIdx.x;
    const int j = blockIdx.y;
    const int tid = threadIdx.x;
    const int m8 = tid & 7;
    const int r  = tid >> 3;        // [0,32)
    const int m  = j * 8 + m8;
    const float2* __restrict__ Z = &g_Z[h * 1024];

    // Step A: one sA entry per thread (k1 = r)
    {
        float rs, rc;
        sincospif((float)m * (1.0f / 16.0f), &rs, &rc);   // e^{2pi i m/32}
        float cr = 1.0f, ci = 0.0f, ar = 0.0f, ai = 0.0f;
        #pragma unroll 8
        for (int k2 = 0; k2 < 32; k2++) {
            const float2 x = Z[r + 32 * k2];
            ar = fmaf(x.x, cr, fmaf(-x.y, ci, ar));
            ai = fmaf(x.x, ci, fmaf( x.y, cr, ai));
            const float ncr = fmaf(cr, rc, -ci * rs);
            const float nci = fmaf(cr, rs,  ci * rc);
            cr = ncr; ci = nci;
        }
        sA[r][m8] = make_float2(ar, ai);
    }
    __syncthreads();

    // Step B: one output per thread
    {
        const int n = (r << 5) + m;
        float rs, rc;
        sincospif((float)n * (1.0f / 512.0f), &rs, &rc);  // e^{2pi i n/1024}
        float cr = 1.0f, ci = 0.0f, zr = 0.0f, zi = 0.0f;
        #pragma unroll 8
        for (int k1 = 0; k1 < 32; k1++) {
            const float2 a = sA[k1][m8];
            zr = fmaf(a.x, cr, fmaf(-a.y, ci, zr));
            zi = fmaf(a.x, ci, fmaf( a.y, cr, zi));
            const float ncr = fmaf(cr, rc, -ci * rs);
            const float nci = fmaf(cr, rs,  ci * rc);
            cr = ncr; ci = nci;
        }
        reinterpret_cast<float2*>(out + h * LL)[n] = make_float2(zr, zi);
    }
}

// ---------------------------------------------------------------------------
// Inputs: 0:C 1:B 2:P 3:inv_w_real 4:w_imag 5:log_dt 6:L(ignored)
// Output: (1, 256, 2048) f32
// ---------------------------------------------------------------------------
extern "C" void kernel_launch(void* const* d_in, const int* in_sizes, int n_in,
                              void* d_out, int out_size)
{
    const float* C     = (const float*)d_in[0];
    const float* B     = (const float*)d_in[1];
    const float* P     = (const float*)d_in[2];
    const float* iwr   = (const float*)d_in[3];
    const float* wimag = (const float*)d_in[4];
    const float* logdt = (const float*)d_in[5];
    float* out = (float*)d_out;

    cauchy_kernel<<<dim3(HH, 5), 256>>>(C, B, P, iwr, wimag, logdt);
    irfft_kernel<<<dim3(HH, 4), 256>>>(out);
}

// round 5
// speedup vs baseline: 1.1141x; 1.0044x over previous
#include <cuda_runtime.h>
#include <math.h>

// SSKernelNPLR: H=256, S=256 (rep=1), N=64, R=1, CH=1, L=2048
#define HH 256
#define NN 64
#define LL 2048

// Packed half-spectrum Z[h][k], k in [0,1024): irfft(X, 2048) == interleaved
// 1024-point complex IDFT of Z.
__device__ float2 g_Z[HH * 1024];

// ---- packed f32x2 helpers (sm_100+) ----
__device__ __forceinline__ unsigned long long pack2(float lo, float hi) {
    unsigned long long r;
    asm("mov.b64 %0, {%1, %2};" : "=l"(r) : "f"(lo), "f"(hi));
    return r;
}
__device__ __forceinline__ void unpack2(unsigned long long v, float& lo, float& hi) {
    asm("mov.b64 {%0, %1}, %2;" : "=f"(lo), "=f"(hi) : "l"(v));
}
__device__ __forceinline__ unsigned long long ffma2(
    unsigned long long a, unsigned long long b, unsigned long long c) {
    unsigned long long d;
    asm("fma.rn.f32x2 %0, %1, %2, %3;" : "=l"(d) : "l"(a), "l"(b), "l"(c));
    return d;
}
__device__ __forceinline__ float frcp_a(float x) {
    float r;
    asm("rcp.approx.f32 %0, %1;" : "=f"(r) : "f"(x));
    return r;
}

// ---------------------------------------------------------------------------
// Kernel 1: Cauchy + Woodbury + bilinear -> packed spectrum Z.
//
// Basis-function form (per n, slot s; u = y^2, t = 1/|d|^2, tu = t*u):
//   re_s += t*P_s + tu*Q_s      P = Nr*K1,  Q = vy*K2 - Nr
//   im_s += y*(t*R_s - tu*vy)   R = vy*K1 - Nr*K2
//   |d|^2 = (K1-u)^2 + K2^2*u   (stable sum-of-squares form)
// Accumulated packed: A_s += (P,Q)*(t,tu);  B_s += (R,-vy)*(t,tu)
// Epilogue: re = A.x+A.y ; im = y*(B.x+B.y)
//
// grid (HH, 5): by<4 main; t<128 -> lA = by*128+t, t>=128 -> 1024-lA
// (pair exchanged via smem, emits packed Z directly). by==4: l=512 self-pair.
// ---------------------------------------------------------------------------
__global__ void __launch_bounds__(256) cauchy_kernel(
    const float* __restrict__ Cin, const float* __restrict__ Bin,
    const float* __restrict__ Pin, const float* __restrict__ iwr,
    const float* __restrict__ wim, const float* __restrict__ logdt)
{
    __shared__ float2 sK[NN];        // (K1, K2^2)
    __shared__ float4 sP[4][NN];     // (P, Q, R, -vy) per slot
    __shared__ float2 sX[256];       // pair exchange

    const int h = blockIdx.x;
    const int tid = threadIdx.x;

    if (tid < NN) {
        const int n = tid;
        const int idx = h * NN + n;
        const float dt = expf(logdt[h]);
        const float a = -expf(iwr[idx]) * dt;
        const float b = wim[idx] * dt;
        const float K1 = fmaf(a, a, b * b);
        const float K2 = -2.0f * a;
        sK[n] = make_float2(K1, K2 * K2);

        const float Br = Bin[2*idx], Bi = Bin[2*idx+1];
        const float Cr = Cin[2*idx], Ci = Cin[2*idx+1];
        const float Pr = Pin[2*idx], Pi = Pin[2*idx+1];

        float p, q, Nr, vy;
        p = Br*Cr - Bi*Ci;  q = Br*Ci + Bi*Cr;               // v00 = B*C
        Nr = -2.0f*(p*a + q*b)*dt; vy = 2.0f*p*dt;
        sP[0][n] = make_float4(Nr*K1, vy*K2 - Nr, vy*K1 - Nr*K2, -vy);
        p = Br*Pr + Bi*Pi;  q = Bi*Pr - Br*Pi;               // v01 = B*conj(P)
        Nr = -2.0f*(p*a + q*b)*dt; vy = 2.0f*p*dt;
        sP[1][n] = make_float4(Nr*K1, vy*K2 - Nr, vy*K1 - Nr*K2, -vy);
        p = Pr*Cr - Pi*Ci;  q = Pr*Ci + Pi*Cr;               // v10 = P*C
        Nr = -2.0f*(p*a + q*b)*dt; vy = 2.0f*p*dt;
        sP[2][n] = make_float4(Nr*K1, vy*K2 - Nr, vy*K1 - Nr*K2, -vy);
        p = Pr*Pr + Pi*Pi;                                   // v11 = |P|^2
        Nr = -2.0f*p*a*dt; vy = 2.0f*p*dt;
        sP[3][n] = make_float4(Nr*K1, vy*K2 - Nr, vy*K1 - Nr*K2, -vy);
    }
    __syncthreads();

    const int by = blockIdx.y;
    const bool special = (by == 4);
    int l;
    if (special) {
        if (tid >= 32) return;       // one warp; no syncs below on this path
        l = 512;
    } else {
        const int tq = tid & 127;
        const int lA = by * 128 + tq;
        l = (tid < 128) ? lA : (1024 - lA);
    }

    float y = 2.0f * tanf((float)l * (3.14159265358979323846f / 2048.0f));
    y = fminf(fmaxf(y, -3.0e7f), 3.0e7f);     // guard l -> 1024 pole
    const float u = y * y;

    const ulonglong2* __restrict__ p0 = reinterpret_cast<const ulonglong2*>(sP[0]);
    const ulonglong2* __restrict__ p1 = reinterpret_cast<const ulonglong2*>(sP[1]);
    const ulonglong2* __restrict__ p2 = reinterpret_cast<const ulonglong2*>(sP[2]);
    const ulonglong2* __restrict__ p3 = reinterpret_cast<const ulonglong2*>(sP[3]);

    unsigned long long A0 = 0ull, B0 = 0ull, A1 = 0ull, B1 = 0ull;
    unsigned long long A2 = 0ull, B2 = 0ull, A3 = 0ull, B3 = 0ull;

    #pragma unroll 4
    for (int n = 0; n < NN; n++) {
        const float2 kk = sK[n];                      // (K1, K2^2)
        const float dr = kk.x - u;
        const float md = fmaf(dr, dr, kk.y * u);      // |d|^2, stable
        const float t  = frcp_a(md);
        const float tu = t * u;
        const unsigned long long T = pack2(t, tu);

        ulonglong2 q;
        q = p0[n]; A0 = ffma2(q.x, T, A0); B0 = ffma2(q.y, T, B0);
        q = p1[n]; A1 = ffma2(q.x, T, A1); B1 = ffma2(q.y, T, B1);
        q = p2[n]; A2 = ffma2(q.x, T, A2); B2 = ffma2(q.y, T, B2);
        q = p3[n]; A3 = ffma2(q.x, T, A3); B3 = ffma2(q.y, T, B3);
    }

    float ax, ay, bx, byy;
    float r0r, r0i, r1r, r1i, r2r, r2i, r3r, r3i;
    unpack2(A0, ax, ay); unpack2(B0, bx, byy);
    r0r = ax + ay;  r0i = y * (bx + byy);
    unpack2(A1, ax, ay); unpack2(B1, bx, byy);
    r1r = ax + ay;  r1i = y * (bx + byy);
    unpack2(A2, ax, ay); unpack2(B2, bx, byy);
    r2r = ax + ay;  r2i = y * (bx + byy);
    unpack2(A3, ax, ay); unpack2(B3, bx, byy);
    r3r = ax + ay;  r3i = y * (bx + byy);

    // Woodbury: kf = r00 - r01*r10/(1 + r11)
    const float dre  = 1.0f + r3r;
    const float dim_ = r3i;
    const float dm = frcp_a(fmaf(dre, dre, dim_ * dim_));
    const float tr = r1r * r2r - r1i * r2i;
    const float ti = r1r * r2i + r1i * r2r;
    const float wr = (tr * dre + ti * dim_) * dm;
    const float wi = (ti * dre - tr * dim_) * dm;
    const float kr = r0r - wr;
    const float ki = r0i - wi;

    // * 2/(1+omega) = (1 + i*y/2)
    const float hy = 0.5f * y;
    const float2 X = make_float2(kr - ki * hy, ki + kr * hy);

    float2* __restrict__ Z = &g_Z[h * 1024];

    if (special) {
        if (tid == 0)
            Z[512] = make_float2(X.x * (1.0f / 1024.0f), -X.y * (1.0f / 1024.0f));
        return;
    }

    sX[tid] = X;
    __syncthreads();

    if (tid < 128) {
        const int lA = by * 128 + tid;
        const float2 X1 = sX[tid + 128];      // X[1024 - lA]
        const float Sx = X.x + X1.x, Sy = X.y - X1.y;
        const float Dx = X.x - X1.x, Dy = X.y + X1.y;
        float ts, tc;
        sincospif((float)lA * (1.0f / 1024.0f), &ts, &tc);   // e^{i pi lA/1024}
        const float Tx = tc * Dx - ts * Dy;
        const float Ty = tc * Dy + ts * Dx;
        const float sc = 1.0f / 2048.0f;
        Z[lA] = make_float2((Sx - Ty) * sc, (Sy + Tx) * sc);
        if (lA != 0)
            Z[1024 - lA] = make_float2((Sx + Ty) * sc, (Tx - Sy) * sc);
    }
}

// ---------------------------------------------------------------------------
// Kernel 2: 1024-point complex IDFT of Z per h (two-step 32x32), m-split 4-way,
// table-based twiddles (all reduce mod 32 after fold):
//   A [k1][m] = sum_{k2<32} Z[k1+32k2] tw[(k2*m)&31]
//   A''[k1][m] = A[k1][m] * e^{2pi i k1 m/1024}      (fold, once per entry)
//   z[32q+m]  = sum_{k1<32} A''[k1][m] tw[(k1*q)&31]
//   out[2n] = Re z[n], out[2n+1] = Im z[n]
// ---------------------------------------------------------------------------
__global__ void __launch_bounds__(256) irfft_kernel(float* __restrict__ out)
{
    __shared__ float2 sA[32][8];    // 2 KB
    __shared__ float2 tw[32];       // e^{2pi i j/32}

    const int h = blockIdx.x;
    const int j = blockIdx.y;
    const int tid = threadIdx.x;
    const int m8 = tid & 7;
    const int r  = tid >> 3;        // [0,32)
    const int m  = j * 8 + m8;
    const float2* __restrict__ Z = &g_Z[h * 1024];

    if (tid < 32) {
        float s, c;
        sincospif((float)tid * (1.0f / 16.0f), &s, &c);
        tw[tid] = make_float2(c, s);
    }
    __syncthreads();

    // Step A: k1 = r; twiddle index walks (k2*m) mod 32
    {
        float ar = 0.0f, ai = 0.0f;
        int idx = 0;
        #pragma unroll 8
        for (int k2 = 0; k2 < 32; k2++) {
            const float2 x = Z[r + 32 * k2];
            const float2 w = tw[idx];
            ar = fmaf(x.x, w.x, fmaf(-x.y, w.y, ar));
            ai = fmaf(x.x, w.y, fmaf( x.y, w.x, ai));
            idx = (idx + m) & 31;
        }
        // fold twiddle e^{2pi i r*m/1024}
        float fs, fc;
        sincospif((float)(r * m) * (1.0f / 512.0f), &fs, &fc);
        sA[r][m8] = make_float2(ar * fc - ai * fs, ar * fs + ai * fc);
    }
    __syncthreads();

    // Step B: output n = 32*r + m; twiddle index walks (k1*r) mod 32
    {
        float zr = 0.0f, zi = 0.0f;
        int idx = 0;
        #pragma unroll 8
        for (int k1 = 0; k1 < 32; k1++) {
            const float2 a = sA[k1][m8];
            const float2 w = tw[idx];
            zr = fmaf(a.x, w.x, fmaf(-a.y, w.y, zr));
            zi = fmaf(a.x, w.y, fmaf( a.y, w.x, zi));
            idx = (idx + r) & 31;
        }
        reinterpret_cast<float2*>(out + h * LL)[(r << 5) + m] = make_float2(zr, zi);
    }
}

// ---------------------------------------------------------------------------
// Inputs: 0:C 1:B 2:P 3:inv_w_real 4:w_imag 5:log_dt 6:L(ignored)
// Output: (1, 256, 2048) f32
// ---------------------------------------------------------------------------
extern "C" void kernel_launch(void* const* d_in, const int* in_sizes, int n_in,
                              void* d_out, int out_size)
{
    const float* C     = (const float*)d_in[0];
    const float* B     = (const float*)d_in[1];
    const float* P     = (const float*)d_in[2];
    const float* iwr   = (const float*)d_in[3];
    const float* wimag = (const float*)d_in[4];
    const float* logdt = (const float*)d_in[5];
    float* out = (float*)d_out;

    cauchy_kernel<<<dim3(HH, 5), 256>>>(C, B, P, iwr, wimag, logdt);
    irfft_kernel<<<dim3(HH, 4), 256>>>(out);
}